// round 8
// baseline (speedup 1.0000x reference)
#include <cuda_runtime.h>
#include <cuda_bf16.h>

// FHN IMEX dynamics, (4,4096,2048) fp32, 8 steps.
// One CTA (256 threads) per 2048-element row; 8 elements/thread (two float4).
// s = P - dt*w folding: 5 packed f32x2 FMA ops + 4 scalar FMNMX per pair/step.
// Fast path (n_steps==8, dt==1): step 1 folded into prologue (v0=0),
// step 2 clip skipped (|v_pre2| <= 2.80 < 3 proven), step 8 S-update dead.
// Streaming loads/stores (.cs) for once-touched data.

#define FHN_TAU 12.5f

typedef unsigned long long ull;

union UF { ull u; float2 f; };

__device__ __forceinline__ ull pk2(float lo, float hi) {
    UF r; r.f.x = lo; r.f.y = hi; return r.u;
}
__device__ __forceinline__ ull fma2(ull a, ull b, ull c) {
    ull d; asm("fma.rn.f32x2 %0, %1, %2, %3;" : "=l"(d) : "l"(a), "l"(b), "l"(c)); return d;
}
__device__ __forceinline__ ull mul2(ull a, ull b) {
    ull d; asm("mul.rn.f32x2 %0, %1, %2;" : "=l"(d) : "l"(a), "l"(b)); return d;
}
__device__ __forceinline__ ull clip2(ull x) {
    UF v; v.u = x;
    v.f.x = fminf(fmaxf(v.f.x, -3.0f), 3.0f);
    v.f.y = fminf(fmaxf(v.f.y, -3.0f), 3.0f);
    return v.u;
}

__global__ __launch_bounds__(256, 5)
void fhn_kernel(const float* __restrict__ stim,
                const float* __restrict__ a_p,
                const float* __restrict__ b_p,
                const float* __restrict__ dt_p,
                const int*   __restrict__ ns_p,
                float* __restrict__ out,
                long long N, int writeV)
{
    const int  C    = 2048;
    const int  t    = threadIdx.x;
    const long long base = (long long)blockIdx.x * C;

    // ---- load 8 elements as two coalesced float4 (streaming) ----
    const float4* s4 = reinterpret_cast<const float4*>(stim + base);
    float4 x0 = __ldcs(s4 + t);
    float4 x1 = __ldcs(s4 + t + 256);

    // ---- row max(|x|) reduction ----
    float m = fmaxf(fmaxf(fmaxf(fabsf(x0.x), fabsf(x0.y)), fmaxf(fabsf(x0.z), fabsf(x0.w))),
                    fmaxf(fmaxf(fabsf(x1.x), fabsf(x1.y)), fmaxf(fabsf(x1.z), fabsf(x1.w))));
    #pragma unroll
    for (int o = 16; o > 0; o >>= 1)
        m = fmaxf(m, __shfl_xor_sync(0xffffffffu, m, o));
    __shared__ float wmax[8];
    if ((t & 31) == 0) wmax[t >> 5] = m;
    __syncthreads();
    m = wmax[0];
    #pragma unroll
    for (int i = 1; i < 8; ++i) m = fmaxf(m, wmax[i]);

    const float scale = fmaxf(m, 1e-6f);
    const float inv_scale = __fdividef(1.0f, scale);

    // ---- scalars / per-step constants ----
    const float a  = *a_p;
    const float b  = *b_p;
    const float dt = *dt_p;
    const int   n_steps = ns_p ? *ns_p : 8;

    const float alpha = dt / FHN_TAU;
    const float denom = 1.0f + alpha * b;
    const float k1 = 1.0f / denom;
    const float k2 = alpha / denom;
    const float k3 = alpha * a / denom;
    const float c1 = 1.0f + dt;              // v_pre = v*(c1 - c3*v^2) + s
    const float c3 = dt * (1.0f / 3.0f);

    // s-recurrence: s = P - dt*w;  s' = k1*s + nck*v_pre + P2
    const float omk1 = 1.0f - k1;
    const float ndk3 = -dt * k3;
    const float nck  = -dt * k2;

    const ull C1  = pk2(c1, c1);
    const ull NC3 = pk2(-c3, -c3);
    const ull K1  = pk2(k1, k1);
    const ull NCK = pk2(nck, nck);

    // ---- stimulus conditioning:
    //   I = (x/scale)*(0.1 + 0.9*sigmoid((|x|-0.5)*10));  P = dt*I
    //   P2 = (1-k1)*P - dt*k3
    const float di = dt * inv_scale;
    const bool fast8 = (n_steps == 8) && (dt == 1.0f);
    const float s1c = 1.0f + nck;            // s1 = (1+nck)*P + ndk3 (fast path)

    float xs[8] = {x0.x, x0.y, x0.z, x0.w, x1.x, x1.y, x1.z, x1.w};
    float p[8], p2[8], sini[8];
    #pragma unroll
    for (int i = 0; i < 8; ++i) {
        float xv = xs[i];
        float ax = fabsf(xv);
        float e  = __expf(fmaf(-10.0f, ax, 5.0f));      // exp(-(|x|-0.5)*10)
        float g  = __fdividef(1.0f, 1.0f + e);          // sigmoid
        float P  = (di * xv) * fmaf(0.9f, g, 0.1f);
        p[i]    = P;
        p2[i]   = fmaf(omk1, P, ndk3);
        sini[i] = fmaf(s1c, P, ndk3);                   // s after step 1
    }

    ull P2[4], V[4], S[4];

#define FHN_STEP_FULL(j)                                        \
    do {                                                        \
        ull T  = mul2(V[j], V[j]);                              \
        ull R  = fma2(NC3, T, C1);                              \
        ull Vp = fma2(R, V[j], S[j]);                           \
        S[j]   = fma2(K1, S[j], fma2(NCK, Vp, P2[j]));          \
        V[j]   = clip2(Vp);                                     \
    } while (0)

#define FHN_STEP_NOCLIP(j)                                      \
    do {                                                        \
        ull T  = mul2(V[j], V[j]);                              \
        ull R  = fma2(NC3, T, C1);                              \
        ull Vp = fma2(R, V[j], S[j]);                           \
        S[j]   = fma2(K1, S[j], fma2(NCK, Vp, P2[j]));          \
        V[j]   = Vp;                                            \
    } while (0)

#define FHN_STEP_LAST(j)                                        \
    do {                                                        \
        ull T  = mul2(V[j], V[j]);                              \
        ull R  = fma2(NC3, T, C1);                              \
        ull Vp = fma2(R, V[j], S[j]);                           \
        V[j]   = clip2(Vp);                                     \
    } while (0)

    if (fast8) {
        // step 1 folded into prologue: v1 = P (|P|<=1, no clip), s1 precomputed
        #pragma unroll
        for (int j = 0; j < 4; ++j) {
            V[j]  = pk2(p[2 * j], p[2 * j + 1]);
            S[j]  = pk2(sini[2 * j], sini[2 * j + 1]);
            P2[j] = pk2(p2[2 * j], p2[2 * j + 1]);
        }
        // step 2: clip provably inactive (|v_pre2| <= 2.80)
        FHN_STEP_NOCLIP(0); FHN_STEP_NOCLIP(1); FHN_STEP_NOCLIP(2); FHN_STEP_NOCLIP(3);
        // steps 3..7: full
        #pragma unroll
        for (int s = 0; s < 5; ++s) {
            FHN_STEP_FULL(0); FHN_STEP_FULL(1); FHN_STEP_FULL(2); FHN_STEP_FULL(3);
        }
        // step 8: S-update is dead
        FHN_STEP_LAST(0); FHN_STEP_LAST(1); FHN_STEP_LAST(2); FHN_STEP_LAST(3);
    } else {
        // generic path: exact semantics, every step fully clipped
        #pragma unroll
        for (int j = 0; j < 4; ++j) {
            V[j]  = 0ull;
            S[j]  = pk2(p[2 * j], p[2 * j + 1]);       // s0 = P (w0 = 0)
            P2[j] = pk2(p2[2 * j], p2[2 * j + 1]);
        }
        for (int s = 0; s < n_steps; ++s) {
            FHN_STEP_FULL(0); FHN_STEP_FULL(1); FHN_STEP_FULL(2); FHN_STEP_FULL(3);
        }
    }
#undef FHN_STEP_FULL
#undef FHN_STEP_NOCLIP
#undef FHN_STEP_LAST

    // ---- outputs: response = v*scale at [0,N), v at [N,2N) (streaming) ----
    const ull SC = pk2(scale, scale);
    UF v0, v1, v2, v3, r0, r1, r2, r3;
    v0.u = V[0]; v1.u = V[1]; v2.u = V[2]; v3.u = V[3];
    r0.u = mul2(V[0], SC); r1.u = mul2(V[1], SC);
    r2.u = mul2(V[2], SC); r3.u = mul2(V[3], SC);

    float4* o4 = reinterpret_cast<float4*>(out + base);
    __stcs(o4 + t,       make_float4(r0.f.x, r0.f.y, r1.f.x, r1.f.y));
    __stcs(o4 + t + 256, make_float4(r2.f.x, r2.f.y, r3.f.x, r3.f.y));

    if (writeV) {
        float4* v4 = reinterpret_cast<float4*>(out + N + base);
        __stcs(v4 + t,       make_float4(v0.f.x, v0.f.y, v1.f.x, v1.f.y));
        __stcs(v4 + t + 256, make_float4(v2.f.x, v2.f.y, v3.f.x, v3.f.y));
    }
}

extern "C" void kernel_launch(void* const* d_in, const int* in_sizes, int n_in,
                              void* d_out, int out_size)
{
    const float* stim = (const float*)d_in[0];
    const float* a    = (const float*)d_in[1];
    const float* b    = (const float*)d_in[2];
    const float* dt   = (const float*)d_in[3];
    const int*   ns   = (n_in > 4) ? (const int*)d_in[4] : nullptr;

    long long N = (long long)in_sizes[0];          // 33,554,432
    int rows = (int)(N / 2048);                    // 16384 CTAs
    int writeV = ((long long)out_size >= 2 * N) ? 1 : 0;

    fhn_kernel<<<rows, 256>>>(stim, a, b, dt, ns, (float*)d_out, N, writeV);
}

// round 9
// speedup vs baseline: 1.4386x; 1.4386x over previous
#include <cuda_runtime.h>
#include <cuda_bf16.h>

// FHN IMEX dynamics, (4,4096,2048) fp32, 8 steps.
// R6 body (best: 79.9us) + 6 CTAs/SM occupancy target (40-reg budget).
// One CTA (256 threads) per 2048-element row; 8 elements/thread (two float4).
// s = P - dt*w folding: 5 packed f32x2 FMA + 4 scalar FMNMX per pair/step.
// Fully-unrolled 8-step fast path; streaming .cs loads/stores.
// Prologue packs state per-pair immediately (no persistent scalar arrays).

#define FHN_TAU 12.5f

typedef unsigned long long ull;

union UF { ull u; float2 f; };

__device__ __forceinline__ ull pk2(float lo, float hi) {
    UF r; r.f.x = lo; r.f.y = hi; return r.u;
}
__device__ __forceinline__ ull fma2(ull a, ull b, ull c) {
    ull d; asm("fma.rn.f32x2 %0, %1, %2, %3;" : "=l"(d) : "l"(a), "l"(b), "l"(c)); return d;
}
__device__ __forceinline__ ull mul2(ull a, ull b) {
    ull d; asm("mul.rn.f32x2 %0, %1, %2;" : "=l"(d) : "l"(a), "l"(b)); return d;
}
__device__ __forceinline__ ull clip2(ull x) {
    UF v; v.u = x;
    v.f.x = fminf(fmaxf(v.f.x, -3.0f), 3.0f);
    v.f.y = fminf(fmaxf(v.f.y, -3.0f), 3.0f);
    return v.u;
}

__global__ __launch_bounds__(256, 6)
void fhn_kernel(const float* __restrict__ stim,
                const float* __restrict__ a_p,
                const float* __restrict__ b_p,
                const float* __restrict__ dt_p,
                const int*   __restrict__ ns_p,
                float* __restrict__ out,
                long long N, int writeV)
{
    const int  C    = 2048;
    const int  t    = threadIdx.x;
    const long long base = (long long)blockIdx.x * C;

    // ---- load 8 elements as two coalesced float4 (streaming) ----
    const float4* s4 = reinterpret_cast<const float4*>(stim + base);
    float4 x0 = __ldcs(s4 + t);
    float4 x1 = __ldcs(s4 + t + 256);

    // ---- row max(|x|) reduction ----
    float m = fmaxf(fmaxf(fmaxf(fabsf(x0.x), fabsf(x0.y)), fmaxf(fabsf(x0.z), fabsf(x0.w))),
                    fmaxf(fmaxf(fabsf(x1.x), fabsf(x1.y)), fmaxf(fabsf(x1.z), fabsf(x1.w))));
    #pragma unroll
    for (int o = 16; o > 0; o >>= 1)
        m = fmaxf(m, __shfl_xor_sync(0xffffffffu, m, o));
    __shared__ float wmax[8];
    if ((t & 31) == 0) wmax[t >> 5] = m;
    __syncthreads();
    m = wmax[0];
    #pragma unroll
    for (int i = 1; i < 8; ++i) m = fmaxf(m, wmax[i]);

    const float scale = fmaxf(m, 1e-6f);
    const float inv_scale = __fdividef(1.0f, scale);

    // ---- scalars / per-step constants ----
    const float a  = *a_p;
    const float b  = *b_p;
    const float dt = *dt_p;
    const int   n_steps = ns_p ? *ns_p : 8;

    const float alpha = dt / FHN_TAU;
    const float denom = 1.0f + alpha * b;
    const float k1 = 1.0f / denom;
    const float k2 = alpha / denom;
    const float k3 = alpha * a / denom;
    const float c1 = 1.0f + dt;              // v_pre = v*(c1 - c3*v^2) + s
    const float c3 = dt * (1.0f / 3.0f);

    // s-recurrence: s = P - dt*w;  s' = k1*s + nck*v_pre + P2
    const float omk1 = 1.0f - k1;
    const float ndk3 = -dt * k3;
    const float nck  = -dt * k2;

    const ull C1  = pk2(c1, c1);
    const ull NC3 = pk2(-c3, -c3);
    const ull K1  = pk2(k1, k1);
    const ull NCK = pk2(nck, nck);

    // ---- stimulus conditioning, packed per-pair (no persistent scalar arrays):
    //   I = (x/scale)*(0.1 + 0.9*sigmoid((|x|-0.5)*10));  P = dt*I; s0 = P
    //   P2 = (1-k1)*P - dt*k3
    const float di = dt * inv_scale;
    ull P2[4], V[4], S[4];
    {
        float xs[8] = {x0.x, x0.y, x0.z, x0.w, x1.x, x1.y, x1.z, x1.w};
        #pragma unroll
        for (int j = 0; j < 4; ++j) {
            float Pl, Ph;
            {
                float xv = xs[2 * j];
                float e  = __expf(fmaf(-10.0f, fabsf(xv), 5.0f));
                float g  = __fdividef(1.0f, 1.0f + e);
                Pl = (di * xv) * fmaf(0.9f, g, 0.1f);
            }
            {
                float xv = xs[2 * j + 1];
                float e  = __expf(fmaf(-10.0f, fabsf(xv), 5.0f));
                float g  = __fdividef(1.0f, 1.0f + e);
                Ph = (di * xv) * fmaf(0.9f, g, 0.1f);
            }
            S[j]  = pk2(Pl, Ph);                                  // s0 = P (w0 = 0)
            P2[j] = pk2(fmaf(omk1, Pl, ndk3), fmaf(omk1, Ph, ndk3));
            V[j]  = 0ull;
        }
    }

#define FHN_STEP(j)                                             \
    do {                                                        \
        ull T  = mul2(V[j], V[j]);                              \
        ull R  = fma2(NC3, T, C1);                              \
        ull Vp = fma2(R, V[j], S[j]);                           \
        S[j]   = fma2(K1, S[j], fma2(NCK, Vp, P2[j]));          \
        V[j]   = clip2(Vp);                                     \
    } while (0)

    if (n_steps == 8) {
        #pragma unroll
        for (int s = 0; s < 8; ++s) {
            FHN_STEP(0); FHN_STEP(1); FHN_STEP(2); FHN_STEP(3);
        }
    } else {
        for (int s = 0; s < n_steps; ++s) {
            FHN_STEP(0); FHN_STEP(1); FHN_STEP(2); FHN_STEP(3);
        }
    }
#undef FHN_STEP

    // ---- outputs: response = v*scale at [0,N), v at [N,2N) (streaming) ----
    const ull SC = pk2(scale, scale);
    UF v0, v1, v2, v3, r0, r1, r2, r3;
    v0.u = V[0]; v1.u = V[1]; v2.u = V[2]; v3.u = V[3];
    r0.u = mul2(V[0], SC); r1.u = mul2(V[1], SC);
    r2.u = mul2(V[2], SC); r3.u = mul2(V[3], SC);

    float4* o4 = reinterpret_cast<float4*>(out + base);
    __stcs(o4 + t,       make_float4(r0.f.x, r0.f.y, r1.f.x, r1.f.y));
    __stcs(o4 + t + 256, make_float4(r2.f.x, r2.f.y, r3.f.x, r3.f.y));

    if (writeV) {
        float4* v4 = reinterpret_cast<float4*>(out + N + base);
        __stcs(v4 + t,       make_float4(v0.f.x, v0.f.y, v1.f.x, v1.f.y));
        __stcs(v4 + t + 256, make_float4(v2.f.x, v2.f.y, v3.f.x, v3.f.y));
    }
}

extern "C" void kernel_launch(void* const* d_in, const int* in_sizes, int n_in,
                              void* d_out, int out_size)
{
    const float* stim = (const float*)d_in[0];
    const float* a    = (const float*)d_in[1];
    const float* b    = (const float*)d_in[2];
    const float* dt   = (const float*)d_in[3];
    const int*   ns   = (n_in > 4) ? (const int*)d_in[4] : nullptr;

    long long N = (long long)in_sizes[0];          // 33,554,432
    int rows = (int)(N / 2048);                    // 16384 CTAs
    int writeV = ((long long)out_size >= 2 * N) ? 1 : 0;

    fhn_kernel<<<rows, 256>>>(stim, a, b, dt, ns, (float*)d_out, N, writeV);
}

// round 10
// speedup vs baseline: 1.5406x; 1.0709x over previous
#include <cuda_runtime.h>
#include <cuda_bf16.h>

// FHN IMEX dynamics, (4,4096,2048) fp32, 8 steps.
// Persistent CTAs (152x5), each processing ~18 rows with register prefetch of
// the next row's stimulus, overlapping DRAM traffic with the 8-step compute.
// One row = 2048 elems = 256 threads x 8 elems (two float4).
// s = P - dt*w folding: 5 packed f32x2 FMA + 4 scalar FMNMX per pair/step.

#define FHN_TAU 12.5f

typedef unsigned long long ull;

union UF { ull u; float2 f; };

__device__ __forceinline__ ull pk2(float lo, float hi) {
    UF r; r.f.x = lo; r.f.y = hi; return r.u;
}
__device__ __forceinline__ ull fma2(ull a, ull b, ull c) {
    ull d; asm("fma.rn.f32x2 %0, %1, %2, %3;" : "=l"(d) : "l"(a), "l"(b), "l"(c)); return d;
}
__device__ __forceinline__ ull mul2(ull a, ull b) {
    ull d; asm("mul.rn.f32x2 %0, %1, %2;" : "=l"(d) : "l"(a), "l"(b)); return d;
}
__device__ __forceinline__ ull clip2(ull x) {
    UF v; v.u = x;
    v.f.x = fminf(fmaxf(v.f.x, -3.0f), 3.0f);
    v.f.y = fminf(fmaxf(v.f.y, -3.0f), 3.0f);
    return v.u;
}

__global__ __launch_bounds__(256, 5)
void fhn_kernel(const float* __restrict__ stim,
                const float* __restrict__ a_p,
                const float* __restrict__ b_p,
                const float* __restrict__ dt_p,
                const int*   __restrict__ ns_p,
                float* __restrict__ out,
                long long N, int rows, int writeV)
{
    const int t = threadIdx.x;

    // ---- hoisted scalars / per-step constants (once per CTA) ----
    const float a  = *a_p;
    const float b  = *b_p;
    const float dt = *dt_p;
    const int   n_steps = ns_p ? *ns_p : 8;

    const float alpha = dt / FHN_TAU;
    const float denom = 1.0f + alpha * b;
    const float k1 = 1.0f / denom;
    const float k2 = alpha / denom;
    const float k3 = alpha * a / denom;
    const float c1 = 1.0f + dt;              // v_pre = v*(c1 - c3*v^2) + s
    const float c3 = dt * (1.0f / 3.0f);
    const float omk1 = 1.0f - k1;            // s' = k1*s + nck*v_pre + P2
    const float ndk3 = -dt * k3;
    const float nck  = -dt * k2;

    const ull C1  = pk2(c1, c1);
    const ull NC3 = pk2(-c3, -c3);
    const ull K1  = pk2(k1, k1);
    const ull NCK = pk2(nck, nck);

    __shared__ float wmax[2][8];

    // ---- prefetch first row ----
    int row = blockIdx.x;
    const int stride = gridDim.x;

    const float4* s4 = reinterpret_cast<const float4*>(stim) + (long long)row * 512;
    float4 x0 = __ldcs(s4 + t);
    float4 x1 = __ldcs(s4 + t + 256);

    int buf = 0;
    for (; row < rows; row += stride, buf ^= 1) {
        // ---- prefetch next row (latency hidden behind this row's compute) ----
        float4 nx0, nx1;
        const int nrow = row + stride;
        if (nrow < rows) {
            const float4* n4 = reinterpret_cast<const float4*>(stim) + (long long)nrow * 512;
            nx0 = __ldcs(n4 + t);
            nx1 = __ldcs(n4 + t + 256);
        }

        // ---- row max(|x|) reduction ----
        float m = fmaxf(fmaxf(fmaxf(fabsf(x0.x), fabsf(x0.y)), fmaxf(fabsf(x0.z), fabsf(x0.w))),
                        fmaxf(fmaxf(fabsf(x1.x), fabsf(x1.y)), fmaxf(fabsf(x1.z), fabsf(x1.w))));
        #pragma unroll
        for (int o = 16; o > 0; o >>= 1)
            m = fmaxf(m, __shfl_xor_sync(0xffffffffu, m, o));
        if ((t & 31) == 0) wmax[buf][t >> 5] = m;
        __syncthreads();
        m = wmax[buf][0];
        #pragma unroll
        for (int i = 1; i < 8; ++i) m = fmaxf(m, wmax[buf][i]);

        const float scale = fmaxf(m, 1e-6f);
        const float di = dt * __fdividef(1.0f, scale);

        // ---- stimulus conditioning, packed per-pair ----
        ull P2[4], V[4], S[4];
        {
            float xs[8] = {x0.x, x0.y, x0.z, x0.w, x1.x, x1.y, x1.z, x1.w};
            #pragma unroll
            for (int j = 0; j < 4; ++j) {
                float Pl, Ph;
                {
                    float xv = xs[2 * j];
                    float e  = __expf(fmaf(-10.0f, fabsf(xv), 5.0f));
                    float g  = __fdividef(1.0f, 1.0f + e);
                    Pl = (di * xv) * fmaf(0.9f, g, 0.1f);
                }
                {
                    float xv = xs[2 * j + 1];
                    float e  = __expf(fmaf(-10.0f, fabsf(xv), 5.0f));
                    float g  = __fdividef(1.0f, 1.0f + e);
                    Ph = (di * xv) * fmaf(0.9f, g, 0.1f);
                }
                S[j]  = pk2(Pl, Ph);                                  // s0 = P (w0 = 0)
                P2[j] = pk2(fmaf(omk1, Pl, ndk3), fmaf(omk1, Ph, ndk3));
                V[j]  = 0ull;
            }
        }

#define FHN_STEP(j)                                             \
    do {                                                        \
        ull T  = mul2(V[j], V[j]);                              \
        ull R  = fma2(NC3, T, C1);                              \
        ull Vp = fma2(R, V[j], S[j]);                           \
        S[j]   = fma2(K1, S[j], fma2(NCK, Vp, P2[j]));          \
        V[j]   = clip2(Vp);                                     \
    } while (0)

        if (n_steps == 8) {
            #pragma unroll
            for (int s = 0; s < 8; ++s) {
                FHN_STEP(0); FHN_STEP(1); FHN_STEP(2); FHN_STEP(3);
            }
        } else {
            for (int s = 0; s < n_steps; ++s) {
                FHN_STEP(0); FHN_STEP(1); FHN_STEP(2); FHN_STEP(3);
            }
        }
#undef FHN_STEP

        // ---- outputs: response = v*scale at [0,N), v at [N,2N) (streaming) ----
        const ull SC = pk2(scale, scale);
        UF v0, v1, v2, v3, r0, r1, r2, r3;
        v0.u = V[0]; v1.u = V[1]; v2.u = V[2]; v3.u = V[3];
        r0.u = mul2(V[0], SC); r1.u = mul2(V[1], SC);
        r2.u = mul2(V[2], SC); r3.u = mul2(V[3], SC);

        const long long base = (long long)row * 2048;
        float4* o4 = reinterpret_cast<float4*>(out + base);
        __stcs(o4 + t,       make_float4(r0.f.x, r0.f.y, r1.f.x, r1.f.y));
        __stcs(o4 + t + 256, make_float4(r2.f.x, r2.f.y, r3.f.x, r3.f.y));

        if (writeV) {
            float4* v4 = reinterpret_cast<float4*>(out + N + base);
            __stcs(v4 + t,       make_float4(v0.f.x, v0.f.y, v1.f.x, v1.f.y));
            __stcs(v4 + t + 256, make_float4(v2.f.x, v2.f.y, v3.f.x, v3.f.y));
        }

        // rotate prefetch buffers
        x0 = nx0; x1 = nx1;
    }
}

extern "C" void kernel_launch(void* const* d_in, const int* in_sizes, int n_in,
                              void* d_out, int out_size)
{
    const float* stim = (const float*)d_in[0];
    const float* a    = (const float*)d_in[1];
    const float* b    = (const float*)d_in[2];
    const float* dt   = (const float*)d_in[3];
    const int*   ns   = (n_in > 4) ? (const int*)d_in[4] : nullptr;

    long long N = (long long)in_sizes[0];          // 33,554,432
    int rows = (int)(N / 2048);                    // 16384 rows
    int writeV = ((long long)out_size >= 2 * N) ? 1 : 0;

    int grid = 152 * 5;                            // persistent: SMs x CTAs/SM
    if (grid > rows) grid = rows;

    fhn_kernel<<<grid, 256>>>(stim, a, b, dt, ns, (float*)d_out, N, rows, writeV);
}

// round 11
// speedup vs baseline: 1.6479x; 1.0696x over previous
#include <cuda_runtime.h>
#include <cuda_bf16.h>

// FHN IMEX dynamics, (4,4096,2048) fp32, 8 steps.
// Persistent CTAs (152x5), register prefetch of next row's stimulus.
// One row = 2048 elems = 256 threads x 8 elems (two float4).
// s = P - dt*w folding: 5 packed f32x2 FMA + 4 scalar FMNMX per pair/step.
// Fast path (dt==1, |a|<=1, b>=0, n_steps==8), all bitwise-exact:
//   step 1 folded into prologue (v0=0 -> v1=P, |P|<=1 so clip is identity),
//   step 2 clip skipped (|v_pre2| <= 2.83 < 3 proven),
//   step 8 S-update elided (dead).
// Warp max via __reduce_max_sync on float bits (exact for |x| >= 0).

#define FHN_TAU 12.5f

typedef unsigned long long ull;

union UF { ull u; float2 f; };

__device__ __forceinline__ ull pk2(float lo, float hi) {
    UF r; r.f.x = lo; r.f.y = hi; return r.u;
}
__device__ __forceinline__ ull fma2(ull a, ull b, ull c) {
    ull d; asm("fma.rn.f32x2 %0, %1, %2, %3;" : "=l"(d) : "l"(a), "l"(b), "l"(c)); return d;
}
__device__ __forceinline__ ull mul2(ull a, ull b) {
    ull d; asm("mul.rn.f32x2 %0, %1, %2;" : "=l"(d) : "l"(a), "l"(b)); return d;
}
__device__ __forceinline__ ull clip2(ull x) {
    UF v; v.u = x;
    v.f.x = fminf(fmaxf(v.f.x, -3.0f), 3.0f);
    v.f.y = fminf(fmaxf(v.f.y, -3.0f), 3.0f);
    return v.u;
}

__global__ __launch_bounds__(256, 5)
void fhn_kernel(const float* __restrict__ stim,
                const float* __restrict__ a_p,
                const float* __restrict__ b_p,
                const float* __restrict__ dt_p,
                const int*   __restrict__ ns_p,
                float* __restrict__ out,
                long long N, int rows, int writeV)
{
    const int t = threadIdx.x;

    // ---- hoisted scalars / per-step constants (once per CTA) ----
    const float a  = *a_p;
    const float b  = *b_p;
    const float dt = *dt_p;
    const int   n_steps = ns_p ? *ns_p : 8;

    const float alpha = dt / FHN_TAU;
    const float denom = 1.0f + alpha * b;
    const float k1 = 1.0f / denom;
    const float k2 = alpha / denom;
    const float k3 = alpha * a / denom;
    const float c1 = 1.0f + dt;              // v_pre = v*(c1 - c3*v^2) + s
    const float c3 = dt * (1.0f / 3.0f);
    const float omk1 = 1.0f - k1;            // s' = k1*s + nck*v_pre + P2
    const float ndk3 = -dt * k3;
    const float nck  = -dt * k2;

    const ull C1   = pk2(c1, c1);
    const ull NC3  = pk2(-c3, -c3);
    const ull K1   = pk2(k1, k1);
    const ull NCK  = pk2(nck, nck);
    const ull OMK1 = pk2(omk1, omk1);
    const ull NDK3 = pk2(ndk3, ndk3);

    const bool fast8 = (n_steps == 8) && (dt == 1.0f) &&
                       (fabsf(a) <= 1.0f) && (b >= 0.0f);

    __shared__ float wmax[2][8];

    // ---- prefetch first row ----
    int row = blockIdx.x;
    const int stride = gridDim.x;

    const float4* s4 = reinterpret_cast<const float4*>(stim) + (long long)row * 512;
    float4 x0 = __ldcs(s4 + t);
    float4 x1 = __ldcs(s4 + t + 256);

    int buf = 0;
    for (; row < rows; row += stride, buf ^= 1) {
        // ---- prefetch next row (latency hidden behind this row's compute) ----
        float4 nx0, nx1;
        const int nrow = row + stride;
        if (nrow < rows) {
            const float4* n4 = reinterpret_cast<const float4*>(stim) + (long long)nrow * 512;
            nx0 = __ldcs(n4 + t);
            nx1 = __ldcs(n4 + t + 256);
        }

        // ---- row max(|x|) reduction (warp part via redux on float bits) ----
        float m = fmaxf(fmaxf(fmaxf(fabsf(x0.x), fabsf(x0.y)), fmaxf(fabsf(x0.z), fabsf(x0.w))),
                        fmaxf(fmaxf(fabsf(x1.x), fabsf(x1.y)), fmaxf(fabsf(x1.z), fabsf(x1.w))));
        m = __uint_as_float(__reduce_max_sync(0xffffffffu, __float_as_uint(m)));
        if ((t & 31) == 0) wmax[buf][t >> 5] = m;
        __syncthreads();
        m = wmax[buf][0];
        #pragma unroll
        for (int i = 1; i < 8; ++i) m = fmaxf(m, wmax[buf][i]);

        const float scale = fmaxf(m, 1e-6f);
        const float di = dt * __fdividef(1.0f, scale);

        // ---- stimulus conditioning, packed per-pair ----
        ull P2[4], V[4], S[4];
        {
            float xs[8] = {x0.x, x0.y, x0.z, x0.w, x1.x, x1.y, x1.z, x1.w};
            #pragma unroll
            for (int j = 0; j < 4; ++j) {
                float Pl, Ph;
                {
                    float xv = xs[2 * j];
                    float e  = __expf(fmaf(-10.0f, fabsf(xv), 5.0f));
                    float g  = __fdividef(1.0f, 1.0f + e);
                    Pl = (di * xv) * fmaf(0.9f, g, 0.1f);
                }
                {
                    float xv = xs[2 * j + 1];
                    float e  = __expf(fmaf(-10.0f, fabsf(xv), 5.0f));
                    float g  = __fdividef(1.0f, 1.0f + e);
                    Ph = (di * xv) * fmaf(0.9f, g, 0.1f);
                }
                S[j]  = pk2(Pl, Ph);                         // s0 = P (w0 = 0)
                P2[j] = fma2(OMK1, S[j], NDK3);              // P2 = (1-k1)*P - dt*k3
                V[j]  = 0ull;
            }
        }

#define FHN_STEP(j)                                             \
    do {                                                        \
        ull T  = mul2(V[j], V[j]);                              \
        ull R  = fma2(NC3, T, C1);                              \
        ull Vp = fma2(R, V[j], S[j]);                           \
        S[j]   = fma2(K1, S[j], fma2(NCK, Vp, P2[j]));          \
        V[j]   = clip2(Vp);                                     \
    } while (0)

#define FHN_STEP_NOCLIP(j)                                      \
    do {                                                        \
        ull T  = mul2(V[j], V[j]);                              \
        ull R  = fma2(NC3, T, C1);                              \
        ull Vp = fma2(R, V[j], S[j]);                           \
        S[j]   = fma2(K1, S[j], fma2(NCK, Vp, P2[j]));          \
        V[j]   = Vp;                                            \
    } while (0)

#define FHN_STEP_LAST(j)                                        \
    do {                                                        \
        ull T  = mul2(V[j], V[j]);                              \
        ull R  = fma2(NC3, T, C1);                              \
        ull Vp = fma2(R, V[j], S[j]);                           \
        V[j]   = clip2(Vp);                                     \
    } while (0)

        if (fast8) {
            // step 1 folded: v_pre1 = S0 exactly (V=0); clip identity (|P|<=1).
            // Same ops as the loop would emit -> bitwise identical.
            #pragma unroll
            for (int j = 0; j < 4; ++j) {
                ull S0 = S[j];
                V[j] = S0;
                S[j] = fma2(K1, S0, fma2(NCK, S0, P2[j]));
            }
            // step 2: clip provably inactive (|v_pre2| <= 2.83 < 3)
            FHN_STEP_NOCLIP(0); FHN_STEP_NOCLIP(1); FHN_STEP_NOCLIP(2); FHN_STEP_NOCLIP(3);
            // steps 3..7: full
            #pragma unroll
            for (int s = 0; s < 5; ++s) {
                FHN_STEP(0); FHN_STEP(1); FHN_STEP(2); FHN_STEP(3);
            }
            // step 8: S-update dead
            FHN_STEP_LAST(0); FHN_STEP_LAST(1); FHN_STEP_LAST(2); FHN_STEP_LAST(3);
        } else if (n_steps == 8) {
            #pragma unroll
            for (int s = 0; s < 8; ++s) {
                FHN_STEP(0); FHN_STEP(1); FHN_STEP(2); FHN_STEP(3);
            }
        } else {
            for (int s = 0; s < n_steps; ++s) {
                FHN_STEP(0); FHN_STEP(1); FHN_STEP(2); FHN_STEP(3);
            }
        }
#undef FHN_STEP
#undef FHN_STEP_NOCLIP
#undef FHN_STEP_LAST

        // ---- outputs: response = v*scale at [0,N), v at [N,2N) (streaming) ----
        const ull SC = pk2(scale, scale);
        UF v0, v1, v2, v3, r0, r1, r2, r3;
        v0.u = V[0]; v1.u = V[1]; v2.u = V[2]; v3.u = V[3];
        r0.u = mul2(V[0], SC); r1.u = mul2(V[1], SC);
        r2.u = mul2(V[2], SC); r3.u = mul2(V[3], SC);

        const long long base = (long long)row * 2048;
        float4* o4 = reinterpret_cast<float4*>(out + base);
        __stcs(o4 + t,       make_float4(r0.f.x, r0.f.y, r1.f.x, r1.f.y));
        __stcs(o4 + t + 256, make_float4(r2.f.x, r2.f.y, r3.f.x, r3.f.y));

        if (writeV) {
            float4* v4 = reinterpret_cast<float4*>(out + N + base);
            __stcs(v4 + t,       make_float4(v0.f.x, v0.f.y, v1.f.x, v1.f.y));
            __stcs(v4 + t + 256, make_float4(v2.f.x, v2.f.y, v3.f.x, v3.f.y));
        }

        // rotate prefetch buffers
        x0 = nx0; x1 = nx1;
    }
}

extern "C" void kernel_launch(void* const* d_in, const int* in_sizes, int n_in,
                              void* d_out, int out_size)
{
    const float* stim = (const float*)d_in[0];
    const float* a    = (const float*)d_in[1];
    const float* b    = (const float*)d_in[2];
    const float* dt   = (const float*)d_in[3];
    const int*   ns   = (n_in > 4) ? (const int*)d_in[4] : nullptr;

    long long N = (long long)in_sizes[0];          // 33,554,432
    int rows = (int)(N / 2048);                    // 16384 rows
    int writeV = ((long long)out_size >= 2 * N) ? 1 : 0;

    int grid = 152 * 5;                            // persistent: SMs x CTAs/SM
    if (grid > rows) grid = rows;

    fhn_kernel<<<grid, 256>>>(stim, a, b, dt, ns, (float*)d_out, N, rows, writeV);
}